// round 10
// baseline (speedup 1.0000x reference)
#include <cuda_runtime.h>
#include <cuda_fp16.h>

#define NMAX 50000
#define EMAX 800000
#define HID 64
#define BUCKET 96

// ---------------- scratch (static device arrays) ----------------
__device__ float  g_q[NMAX * HID];
__device__ __half g_kvh[NMAX * 128];      // interleaved per node: 16 groups of {k0..k3, v0..v3}
__device__ float  g_skip[NMAX * HID];
__device__ float  g_z[NMAX * 4];
__device__ int    g_cnt[NMAX];
__device__ int2   g_rec[NMAX * BUCKET];   // {src, half2(edge_attr)}
__device__ float  g_Wc[4 * 4160];         // 4 composed weights: 64x64 W + 64 bias each

typedef unsigned long long ull;

// ---------------- packed f32x2 helpers (Blackwell FFMA2 path) ----------------
__device__ __forceinline__ ull pack2(float x, float y) {
    ull r; asm("mov.b64 %0, {%1, %2};" : "=l"(r) : "f"(x), "f"(y)); return r;
}
__device__ __forceinline__ float2 unpack2(ull v) {
    float2 r; asm("mov.b64 {%0, %1}, %2;" : "=f"(r.x), "=f"(r.y) : "l"(v)); return r;
}
__device__ __forceinline__ void fma2(ull& d, ull a, ull b) {
    asm("fma.rn.f32x2 %0, %1, %2, %0;" : "+l"(d) : "l"(a), "l"(b));
}

// ---------------- compose: Wc = Wn @ W2, bc = bn @ W2 + b2 ----------------
__global__ __launch_bounds__(256) void compose_kernel(
    const float* __restrict__ Wn, const float* __restrict__ bn,
    const float* __restrict__ Wq, const float* __restrict__ bq,
    const float* __restrict__ Wk, const float* __restrict__ bk,
    const float* __restrict__ Wv, const float* __restrict__ bv,
    const float* __restrict__ Ws, const float* __restrict__ bs)
{
    int which = blockIdx.x;
    const float* B  = which == 0 ? Wq : which == 1 ? Wk : which == 2 ? Wv : Ws;
    const float* b2 = which == 0 ? bq : which == 1 ? bk : which == 2 ? bv : bs;
    float* out = g_Wc + which * 4160;

    __shared__ float sA[4096];
    __shared__ float sB[4096];
    __shared__ float sbn[64];

    int t = threadIdx.x;
    for (int i = t; i < 1024; i += 256) {
        ((float4*)sA)[i] = ((const float4*)Wn)[i];
        ((float4*)sB)[i] = ((const float4*)B)[i];
    }
    if (t < 64) sbn[t] = bn[t];
    __syncthreads();

    for (int idx = t; idx < 4096; idx += 256) {
        int row = idx >> 6, col = idx & 63;
        float s = 0.0f;
#pragma unroll 8
        for (int k2 = 0; k2 < 64; k2++) s += sA[row * 64 + k2] * sB[k2 * 64 + col];
        out[idx] = s;
    }
    if (t < 64) {
        float s = b2[t];
#pragma unroll 8
        for (int k2 = 0; k2 < 64; k2++) s += sbn[k2] * sB[k2 * 64 + t];
        out[4096 + t] = s;
    }
}

// ---------------- one composed GEMM pass: 8 rows x 8 cols per thread ----------------
// MODE: 0 = fp32 rows, 1 = fp16 interleaved (k slots), 2 = fp16 interleaved (v slots)
template<int MODE>
__device__ __forceinline__ void gemm8_pass(
    const float* __restrict__ sx, float* __restrict__ sW,
    const float* __restrict__ gWc, void* __restrict__ dst,
    int row0, int nrows, int t)
{
    __syncthreads();
    {
        float4* d = (float4*)sW;
        const float4* s4 = (const float4*)gWc;
#pragma unroll
        for (int i = 0; i < 8; i++) d[t + i * 128] = s4[t + i * 128];
    }
    __syncthreads();

    int rg = t >> 3;
    int c0 = (t & 7) * 8;
    const float* xb = sx + rg * 8 * 64;

    float4 b0 = __ldg((const float4*)(gWc + 4096 + c0));
    float4 b1 = __ldg((const float4*)(gWc + 4096 + c0 + 4));
    ull bb0 = pack2(b0.x, b0.y), bb1 = pack2(b0.z, b0.w);
    ull bb2 = pack2(b1.x, b1.y), bb3 = pack2(b1.z, b1.w);

    ull acc[8][4];
#pragma unroll
    for (int r = 0; r < 8; r++) {
        acc[r][0] = bb0; acc[r][1] = bb1; acc[r][2] = bb2; acc[r][3] = bb3;
    }

#pragma unroll 1
    for (int k = 0; k < 64; k += 4) {
        float4 xr[8];
#pragma unroll
        for (int r = 0; r < 8; r++) xr[r] = *(const float4*)(xb + r * 64 + k);
#pragma unroll
        for (int kk = 0; kk < 4; kk++) {
            const float4* wp = (const float4*)(sW + (k + kk) * 64 + c0);
            float4 wa = wp[0], wb = wp[1];
            ull w0 = pack2(wa.x, wa.y), w1 = pack2(wa.z, wa.w);
            ull w2 = pack2(wb.x, wb.y), w3 = pack2(wb.z, wb.w);
#pragma unroll
            for (int r = 0; r < 8; r++) {
                float xv = kk == 0 ? xr[r].x : kk == 1 ? xr[r].y : kk == 2 ? xr[r].z : xr[r].w;
                ull xs = pack2(xv, xv);
                fma2(acc[r][0], xs, w0);
                fma2(acc[r][1], xs, w1);
                fma2(acc[r][2], xs, w2);
                fma2(acc[r][3], xs, w3);
            }
        }
    }

#pragma unroll
    for (int r = 0; r < 8; r++) {
        int gr = row0 + rg * 8 + r;
        if (gr < nrows) {
            float2 p0 = unpack2(acc[r][0]), p1 = unpack2(acc[r][1]);
            float2 p2 = unpack2(acc[r][2]), p3 = unpack2(acc[r][3]);
            if (MODE == 0) {
                float* d = (float*)dst + gr * 64 + c0;
                *(float4*)d       = make_float4(p0.x, p0.y, p1.x, p1.y);
                *(float4*)(d + 4) = make_float4(p2.x, p2.y, p3.x, p3.y);
            } else {
                __half2 h0 = __floats2half2_rn(p0.x, p0.y);
                __half2 h1 = __floats2half2_rn(p1.x, p1.y);
                __half2 h2 = __floats2half2_rn(p2.x, p2.y);
                __half2 h3 = __floats2half2_rn(p3.x, p3.y);
                uint2 u01 = make_uint2(*reinterpret_cast<unsigned*>(&h0),
                                       *reinterpret_cast<unsigned*>(&h1));
                uint2 u23 = make_uint2(*reinterpret_cast<unsigned*>(&h2),
                                       *reinterpret_cast<unsigned*>(&h3));
                int g0 = c0 >> 2;                 // column group (4 cols each)
                int off = (MODE == 1) ? 0 : 4;    // k slots at +0, v slots at +4
                __half* base = (__half*)dst + gr * 128;
                *(uint2*)(base + g0 * 8 + off)       = u01;
                *(uint2*)(base + (g0 + 1) * 8 + off) = u23;
            }
        }
    }
}

// ---------------- node kernel: q/kv/skip directly from x via composed weights ----------------
__global__ __launch_bounds__(128) void node_kernel(const float* __restrict__ x, int nrows)
{
    __shared__ float sx[128 * 64];   // 32 KB
    __shared__ float sW[4096];       // 16 KB

    int t = threadIdx.x;
    int row0 = blockIdx.x * 128;

#pragma unroll
    for (int i = 0; i < 16; i++) {
        int idx = t + i * 128;
        int r = idx >> 4, c = idx & 15;
        int gr = row0 + r;
        float4 v = (gr < nrows) ? __ldg((const float4*)x + gr * 16 + c)
                                : make_float4(0.f, 0.f, 0.f, 0.f);
        *(float4*)(sx + r * 64 + c * 4) = v;
    }

    gemm8_pass<0>(sx, sW, g_Wc + 0 * 4160, (void*)g_q,    row0, nrows, t);
    gemm8_pass<1>(sx, sW, g_Wc + 1 * 4160, (void*)g_kvh,  row0, nrows, t);
    gemm8_pass<2>(sx, sW, g_Wc + 2 * 4160, (void*)g_kvh,  row0, nrows, t);
    gemm8_pass<0>(sx, sW, g_Wc + 3 * 4160, (void*)g_skip, row0, nrows, t);
}

// ---------------- scatter: bucket edges by dst (8B records) ----------------
__global__ __launch_bounds__(256) void scatter_kernel(
    const int* __restrict__ ei, const float* __restrict__ edge_attr, int E)
{
    int e = blockIdx.x * blockDim.x + threadIdx.x;
    if (e >= E) return;
    int src = ei[e];
    int dst = ei[E + e];
    int pos = atomicAdd(&g_cnt[dst], 1);
    if (pos < BUCKET) {
        float2 a = *(const float2*)(edge_attr + e * 2);
        __half2 ah = __floats2half2_rn(a.x, a.y);
        g_rec[dst * BUCKET + pos] = make_int2(src, *reinterpret_cast<int*>(&ah));
    }
}

// ---------------- aggregation: one warp per node; single 16B kv gather per lane ----------------
__global__ __launch_bounds__(256) void agg_kernel(
    const float* __restrict__ We, const float* __restrict__ be,
    const float* __restrict__ Wf, int n_nodes)
{
    __shared__ int2 srec[8][BUCKET];

    int warp = (blockIdx.x * blockDim.x + threadIdx.x) >> 5;
    int wslot = threadIdx.x >> 5;
    int l = threadIdx.x & 31;
    if (warp >= n_nodes) return;
    int n = warp;
    int half = l >> 4;
    int sl = l & 15;
    int c = sl * 4;

    int cnt = __ldg(&g_cnt[n]);
    if (cnt > BUCKET) cnt = BUCKET;
    const int2* rec = g_rec + (long long)n * BUCKET;

    for (int i = l; i < cnt; i += 32) srec[wslot][i] = rec[i];
    if (l == 0 && cnt < BUCKET)
        srec[wslot][cnt] = make_int2(0, 0);   // phantom slot for odd cnt
    __syncwarp();

    float4 q4 = *(const float4*)(g_q + n * 64 + c);

    float4 acc = make_float4(0.f, 0.f, 0.f, 0.f);   // Σ v·ee  (cols c..c+3)
    float s = 0.0f, sa = 0.0f, sb = 0.0f;           // Σee, Σee·ax, Σee·ay (per head)

    int cnt2 = (cnt + 1) >> 1;
#pragma unroll 4
    for (int j = 0; j < cnt2; j++) {
        int i = 2 * j + half;
        int2 r = srec[wslot][i];
        int src = r.x;
        float2 af = __half22float2(*reinterpret_cast<__half2*>(&r.y));

        uint4 kv = *(const uint4*)(g_kvh + src * 128 + sl * 8);   // {k01,k23,v01,v23}
        float2 k01 = __half22float2(*reinterpret_cast<__half2*>(&kv.x));
        float2 k23 = __half22float2(*reinterpret_cast<__half2*>(&kv.y));
        float2 v01 = __half22float2(*reinterpret_cast<__half2*>(&kv.z));
        float2 v23 = __half22float2(*reinterpret_cast<__half2*>(&kv.w));

        float p = q4.x * k01.x + q4.y * k01.y + q4.z * k23.x + q4.w * k23.y;
        p += __shfl_xor_sync(0xffffffffu, p, 1);
        p += __shfl_xor_sync(0xffffffffu, p, 2);

        float ee = (i < cnt) ? __expf(p * 0.25f) : 0.0f;
        s  += ee;
        sa += ee * af.x;
        sb += ee * af.y;

        acc.x += v01.x * ee;
        acc.y += v01.y * ee;
        acc.z += v23.x * ee;
        acc.w += v23.y * ee;
    }

    // combine halves (lane l and l^16 hold same columns / same head)
    acc.x += __shfl_xor_sync(0xffffffffu, acc.x, 16);
    acc.y += __shfl_xor_sync(0xffffffffu, acc.y, 16);
    acc.z += __shfl_xor_sync(0xffffffffu, acc.z, 16);
    acc.w += __shfl_xor_sync(0xffffffffu, acc.w, 16);
    s     += __shfl_xor_sync(0xffffffffu, s, 16);
    sa    += __shfl_xor_sync(0xffffffffu, sa, 16);
    sb    += __shfl_xor_sync(0xffffffffu, sb, 16);

    // epilogue: add factored edge-attr contribution
    float4 we0 = *(const float4*)(We + c);
    float4 we1 = *(const float4*)(We + 64 + c);
    float4 be4 = *(const float4*)(be + c);
    acc.x += we0.x * sa + we1.x * sb + be4.x * s;
    acc.y += we0.y * sa + we1.y * sb + be4.y * s;
    acc.z += we0.z * sa + we1.z * sb + be4.z * s;
    acc.w += we0.w * sa + we1.w * sb + be4.w * s;

    float inv = 1.0f / (s + 1e-16f);
    float4 sk = *(const float4*)(g_skip + n * 64 + c);
    float o0 = acc.x * inv + sk.x;
    float o1 = acc.y * inv + sk.y;
    float o2 = acc.z * inv + sk.z;
    float o3 = acc.w * inv + sk.w;

    float4 wf0 = __ldg((const float4*)(Wf + (c + 0) * 4));
    float4 wf1 = __ldg((const float4*)(Wf + (c + 1) * 4));
    float4 wf2 = __ldg((const float4*)(Wf + (c + 2) * 4));
    float4 wf3 = __ldg((const float4*)(Wf + (c + 3) * 4));
    float z0 = o0 * wf0.x + o1 * wf1.x + o2 * wf2.x + o3 * wf3.x;
    float z1 = o0 * wf0.y + o1 * wf1.y + o2 * wf2.y + o3 * wf3.y;
    float z2 = o0 * wf0.z + o1 * wf1.z + o2 * wf2.z + o3 * wf3.z;
    float z3 = o0 * wf0.w + o1 * wf1.w + o2 * wf2.w + o3 * wf3.w;

#pragma unroll
    for (int off = 1; off < 16; off <<= 1) {
        z0 += __shfl_xor_sync(0xffffffffu, z0, off);
        z1 += __shfl_xor_sync(0xffffffffu, z1, off);
        z2 += __shfl_xor_sync(0xffffffffu, z2, off);
        z3 += __shfl_xor_sync(0xffffffffu, z3, off);
    }
    if (l == 0) *(float4*)(g_z + n * 4) = make_float4(z0, z1, z2, z3);
}

// ---------------- final edge output: 2 edges per thread ----------------
__global__ __launch_bounds__(256) void edge_out_kernel(
    const int* __restrict__ ei, const float* __restrict__ bf,
    float* __restrict__ out, int E)
{
    int e0 = (blockIdx.x * blockDim.x + threadIdx.x) * 2;
    if (e0 >= E) return;
    float4 b = *(const float4*)bf;

    int sa = __ldg(ei + e0);
    int da = __ldg(ei + E + e0);
    float4 zsa = *(const float4*)(g_z + sa * 4);
    float4 zda = *(const float4*)(g_z + da * 4);

    if (e0 + 1 < E) {
        int sb2 = __ldg(ei + e0 + 1);
        int db2 = __ldg(ei + E + e0 + 1);
        float4 zsb = *(const float4*)(g_z + sb2 * 4);
        float4 zdb = *(const float4*)(g_z + db2 * 4);
        *(float4*)(out + e0 * 4)       = make_float4(zsa.x + zda.x + b.x, zsa.y + zda.y + b.y,
                                                     zsa.z + zda.z + b.z, zsa.w + zda.w + b.w);
        *(float4*)(out + (e0 + 1) * 4) = make_float4(zsb.x + zdb.x + b.x, zsb.y + zdb.y + b.y,
                                                     zsb.z + zdb.z + b.z, zsb.w + zdb.w + b.w);
    } else {
        *(float4*)(out + e0 * 4)       = make_float4(zsa.x + zda.x + b.x, zsa.y + zda.y + b.y,
                                                     zsa.z + zda.z + b.z, zsa.w + zda.w + b.w);
    }
}

// ---------------- launch ----------------
extern "C" void kernel_launch(void* const* d_in, const int* in_sizes, int n_in,
                              void* d_out, int out_size)
{
    const float* x  = (const float*)d_in[0];
    const int*   ei = (const int*)d_in[1];
    const float* ea = (const float*)d_in[2];
    const float* Wn = (const float*)d_in[3];
    const float* bn = (const float*)d_in[4];
    const float* We = (const float*)d_in[5];
    const float* be = (const float*)d_in[6];
    const float* Wq = (const float*)d_in[7];
    const float* bq = (const float*)d_in[8];
    const float* Wk = (const float*)d_in[9];
    const float* bk = (const float*)d_in[10];
    const float* Wv = (const float*)d_in[11];
    const float* bv = (const float*)d_in[12];
    const float* Ws = (const float*)d_in[13];
    const float* bs = (const float*)d_in[14];
    const float* Wf = (const float*)d_in[15];
    const float* bf = (const float*)d_in[16];

    int N = in_sizes[0] / HID;
    int E = in_sizes[1] / 2;

    void* cntp;
    cudaGetSymbolAddress(&cntp, g_cnt);
    cudaMemsetAsync(cntp, 0, N * sizeof(int));

    compose_kernel<<<4, 256>>>(Wn, bn, Wq, bq, Wk, bk, Wv, bv, Ws, bs);
    scatter_kernel<<<(E + 255) / 256, 256>>>(ei, ea, E);
    node_kernel<<<(N + 127) / 128, 128>>>(x, N);
    agg_kernel<<<(N * 32 + 255) / 256, 256>>>(We, be, Wf, N);
    edge_out_kernel<<<(E / 2 + 255) / 256, 256>>>(ei, bf, (float*)d_out, E);
}